// round 10
// baseline (speedup 1.0000x reference)
#include <cuda_runtime.h>
#include <cstdint>

#define B_   2
#define S_   2048
#define DM_  1024
#define H_   16
#define D_   64
#define NB_  5
#define SCALE_ 0.125f
#define LOG2E_ 1.4426950408889634f
#define ALPHA_ (SCALE_ * LOG2E_)

// Static device scratch
__device__ float g_q[B_*H_*S_*D_];
__device__ float g_k[B_*H_*S_*D_];
__device__ float g_v[B_*H_*S_*D_];
__device__ float g_att[B_*S_*DM_];
__device__ float g_xr[4096*1024];
__device__ float g_wr[4][1024*1024];   // tf32-rounded W^T (n-major: [n][k])

// ---------------------------------------------------------------------------
// helpers
// ---------------------------------------------------------------------------
__device__ __forceinline__ unsigned f2tf(float x) {
    unsigned r;
    asm("cvt.rna.tf32.f32 %0, %1;" : "=r"(r) : "f"(x));
    return r;
}
__device__ __forceinline__ float f2tff(float x) { return __uint_as_float(f2tf(x)); }

__device__ __forceinline__ void mma8f(float* c, const float* a, float b0f, float b1f) {
    asm volatile(
        "mma.sync.aligned.m16n8k8.row.col.f32.tf32.tf32.f32 "
        "{%0,%1,%2,%3}, {%4,%5,%6,%7}, {%8,%9}, {%0,%1,%2,%3};"
        : "+f"(c[0]), "+f"(c[1]), "+f"(c[2]), "+f"(c[3])
        : "r"(__float_as_uint(a[0])), "r"(__float_as_uint(a[1])),
          "r"(__float_as_uint(a[2])), "r"(__float_as_uint(a[3])),
          "r"(__float_as_uint(b0f)), "r"(__float_as_uint(b1f)));
}

#define CP16(dst_smem, src) \
    asm volatile("cp.async.cg.shared.global [%0], [%1], 16;\n" :: \
        "r"((unsigned)__cvta_generic_to_shared(dst_smem)), "l"(src) : "memory")
#define CP_COMMIT() asm volatile("cp.async.commit_group;\n" ::: "memory")
#define CP_WAIT0()  asm volatile("cp.async.wait_group 0;\n" ::: "memory")
#define CP_WAIT2()  asm volatile("cp.async.wait_group 2;\n" ::: "memory")

// exp2 on FMA pipe. Valid for y <= 0; clamps at -28.
__device__ __forceinline__ float exp2p(float y) {
    y = fmaxf(y, -28.f);
    float t = y + 12582912.0f;
    float fl = t - 12582912.0f;
    float f = y - fl;
    float p = fmaf(1.5403530e-4f, f, 1.3333558e-3f);
    p = fmaf(p, f, 9.6181291e-3f);
    p = fmaf(p, f, 5.5504109e-2f);
    p = fmaf(p, f, 2.4022651e-1f);
    p = fmaf(p, f, 6.9314718e-1f);
    p = fmaf(p, f, 1.0f);
    int e = ((__float_as_int(t) & 0x7FFFFF) - 0x400000 + 127) << 23;
    return p * __int_as_float(e);
}

// ---------------------------------------------------------------------------
// Pre-passes: round x; round+transpose the 4 weight matrices (W^T, n-major).
// ---------------------------------------------------------------------------
__global__ void round_x(const float* __restrict__ x) {
    int i = blockIdx.x * blockDim.x + threadIdx.x;
    const float4* src = (const float4*)x;
    float4* dst = (float4*)g_xr;
    for (; i < 1048576; i += gridDim.x * blockDim.x) {
        float4 v = src[i];
        v.x = f2tff(v.x); v.y = f2tff(v.y); v.z = f2tff(v.z); v.w = f2tff(v.w);
        dst[i] = v;
    }
}

__global__ void transpose_w(const float* __restrict__ wq, const float* __restrict__ wk,
                            const float* __restrict__ wv, const float* __restrict__ wo) {
    __shared__ float t[32][33];
    const int seg = blockIdx.z;
    const float* W = (seg == 0) ? wq : (seg == 1) ? wk : (seg == 2) ? wv : wo;
    const int k0 = blockIdx.y << 5, n0 = blockIdx.x << 5;
    const int tx = threadIdx.x, ty = threadIdx.y;
    #pragma unroll
    for (int i = 0; i < 32; i += 8)
        t[ty + i][tx] = W[(size_t)(k0 + ty + i) * DM_ + n0 + tx];
    __syncthreads();
    #pragma unroll
    for (int i = 0; i < 32; i += 8)
        g_wr[seg][(size_t)(n0 + ty + i) * DM_ + k0 + tx] = f2tff(t[tx][ty + i]);
}

// ---------------------------------------------------------------------------
// TF32 mma.sync GEMM v2: CTA tile 128x64, 256 thr (8 warps, warp tile 32x32),
// k-step 32, 4-stage cp.async pipeline. B read from W^T ([n][k], stride 36).
// Grid: out-proj 512 CTAs, fused QKV 1536 -> ~3.5 waves at 2 CTAs/SM.
// ---------------------------------------------------------------------------
#define GS_ 4
struct GSmem {
    float Xs[GS_][128][36];   // A tile [m][k]
    float Wn[GS_][64][36];    // B tile [n][k]  (W^T rows)
};

__device__ __forceinline__ void gemm_body(
    GSmem& sm, const float* __restrict__ A, const float* __restrict__ WT,
    const float* __restrict__ bias, float* __restrict__ out, int permute,
    int m0, int n0)
{
    const int tid  = threadIdx.x;
    const int lane = tid & 31, wid = tid >> 5;
    const int qd = lane >> 2, lr = lane & 3;
    const int wm = wid >> 1, wn = wid & 1;     // warp grid 4(m) x 2(n)

    const int xr = tid >> 3, xc = (tid & 7) << 2;

    auto load_tile = [&](int stage, int k0) {
        #pragma unroll
        for (int it = 0; it < 4; it++) {
            int r = xr + (it << 5);
            CP16(&sm.Xs[stage][r][xc], &A[(size_t)(m0 + r) * DM_ + k0 + xc]);
        }
        #pragma unroll
        for (int it = 0; it < 2; it++) {
            int r = xr + (it << 5);
            CP16(&sm.Wn[stage][r][xc], &WT[(size_t)(n0 + r) * DM_ + k0 + xc]);
        }
    };

    load_tile(0, 0);  CP_COMMIT();
    load_tile(1, 32); CP_COMMIT();
    load_tile(2, 64); CP_COMMIT();

    float acc[2][4][4] = {};

    for (int c = 0; c < 32; c++) {
        const int buf = c & 3;
        CP_WAIT2();
        __syncthreads();
        if (c + 3 < 32) {
            load_tile((c + 3) & 3, (c + 3) << 5);
            CP_COMMIT();
        }

        #pragma unroll
        for (int ks = 0; ks < 4; ks++) {
            int kk = ks << 3;
            float a[2][4], b[4][2];
            #pragma unroll
            for (int mf = 0; mf < 2; mf++) {
                int r = (wm << 5) + (mf << 4) + qd;
                a[mf][0] = sm.Xs[buf][r][kk + lr];
                a[mf][1] = sm.Xs[buf][r + 8][kk + lr];
                a[mf][2] = sm.Xs[buf][r][kk + lr + 4];
                a[mf][3] = sm.Xs[buf][r + 8][kk + lr + 4];
            }
            #pragma unroll
            for (int nf = 0; nf < 4; nf++) {
                int n = (wn << 5) + (nf << 3) + qd;
                b[nf][0] = sm.Wn[buf][n][kk + lr];
                b[nf][1] = sm.Wn[buf][n][kk + lr + 4];
            }
            #pragma unroll
            for (int mf = 0; mf < 2; mf++)
                #pragma unroll
                for (int nf = 0; nf < 4; nf++)
                    mma8f(acc[mf][nf], a[mf], b[nf][0], b[nf][1]);
        }
    }

    #pragma unroll
    for (int mf = 0; mf < 2; mf++) {
        #pragma unroll
        for (int nf = 0; nf < 4; nf++) {
            #pragma unroll
            for (int rp = 0; rp < 2; rp++) {
                int m = m0 + (wm << 5) + (mf << 4) + qd + (rp << 3);
                int n = n0 + (wn << 5) + (nf << 3) + (lr << 1);
                float v0 = acc[mf][nf][(rp << 1)]     + __ldg(&bias[n]);
                float v1 = acc[mf][nf][(rp << 1) + 1] + __ldg(&bias[n + 1]);
                if (permute) {
                    int bb = m >> 11, s = m & (S_ - 1);
                    int h = n >> 6, d = n & 63;
                    float2 w = make_float2(f2tff(v0), f2tff(v1));
                    *(float2*)&out[(((bb * H_ + h) * S_) + s) * D_ + d] = w;
                } else {
                    *(float2*)&out[(size_t)m * DM_ + n] = make_float2(v0, v1);
                }
            }
        }
    }
}

__global__ __launch_bounds__(256) void gemm_qkv(
    const float* __restrict__ X,
    const float* __restrict__ b0, const float* __restrict__ b1, const float* __restrict__ b2,
    float* __restrict__ o0, float* __restrict__ o1, float* __restrict__ o2)
{
    extern __shared__ char graw[];
    GSmem& sm = *reinterpret_cast<GSmem*>(graw);
    const int z = blockIdx.z;
    const float* bias = (z == 0) ? b0 : (z == 1) ? b1 : b2;
    float* out = (z == 0) ? o0 : (z == 1) ? o1 : o2;
    gemm_body(sm, X, g_wr[z], bias, out, 1, blockIdx.y << 7, blockIdx.x << 6);
}

__global__ __launch_bounds__(256) void gemm_out(
    const float* __restrict__ X, const float* __restrict__ bias, float* __restrict__ out)
{
    extern __shared__ char graw[];
    GSmem& sm = *reinterpret_cast<GSmem*>(graw);
    gemm_body(sm, X, g_wr[3], bias, out, 0, blockIdx.y << 7, blockIdx.x << 6);
}

// ---------------------------------------------------------------------------
// Flash attention (unchanged from R7): q-tile 128, m32/warp, k-tile 32,
// cp.async DB, register shuffle-transpose for P.
// ---------------------------------------------------------------------------
struct ASmem {
    float Ks[2][32][68];
    float Vs[2][32][72];
    float qrelS[128][8];
    float rkS[NB_][64];
    float rvS[NB_][64];
};

__global__ __launch_bounds__(128, 2) void attn_tf32(
    const float* __restrict__ rel_k, const float* __restrict__ rel_v)
{
    extern __shared__ char sraw[];
    ASmem& sm = *reinterpret_cast<ASmem*>(sraw);
    const int tid = threadIdx.x;
    const int lane = tid & 31, wid = tid >> 5;
    const int qd = lane >> 2, lr = lane & 3;
    const bool odd = lr & 1;
    const int src0 = (lane & 28) | (lr >> 1);
    const int src1 = src0 + 2;
    const int q0 = blockIdx.x << 7;
    const int bh = blockIdx.y;
    const float* qptr = g_q + (size_t)bh * S_ * D_;
    const float* kptr = g_k + (size_t)bh * S_ * D_;
    const float* vptr = g_v + (size_t)bh * S_ * D_;

    auto load_kv = [&](int buf, int k0) {
        #pragma unroll
        for (int it = 0; it < 4; it++) {
            int idx = tid + (it << 7);
            int r = idx >> 4, c4 = (idx & 15) << 2;
            CP16(&sm.Ks[buf][r][c4], &kptr[(size_t)(k0 + r) * D_ + c4]);
            CP16(&sm.Vs[buf][r][c4], &vptr[(size_t)(k0 + r) * D_ + c4]);
        }
    };

    load_kv(0, 0);
    CP_COMMIT();

    for (int t = tid; t < NB_ * 64; t += 128) {
        sm.rkS[t >> 6][t & 63] = rel_k[t];
        sm.rvS[t >> 6][t & 63] = rel_v[t];
    }

    const int rw = wid << 5;
    float qf[2][8][4];
    #pragma unroll
    for (int h = 0; h < 2; h++) {
        const float* qr0 = &qptr[(size_t)(q0 + rw + (h << 4) + qd) * D_];
        #pragma unroll
        for (int kf = 0; kf < 8; kf++) {
            qf[h][kf][0] = __ldg(&qr0[(kf << 3) + lr]);
            qf[h][kf][1] = __ldg(&qr0[(size_t)8 * D_ + (kf << 3) + lr]);
            qf[h][kf][2] = __ldg(&qr0[(kf << 3) + lr + 4]);
            qf[h][kf][3] = __ldg(&qr0[(size_t)8 * D_ + (kf << 3) + lr + 4]);
        }
    }
    __syncthreads();

    #pragma unroll
    for (int st = 0; st < 4; st++) {
        int h = st >> 1, rp = st & 1;
        int rloc = rw + (h << 4) + qd + (rp << 3);
        #pragma unroll
        for (int jb = 0; jb < NB_; jb++) {
            float acc = 0.f;
            #pragma unroll
            for (int kf = 0; kf < 8; kf++) {
                acc += qf[h][kf][rp]     * sm.rkS[jb][(kf << 3) + lr];
                acc += qf[h][kf][rp + 2] * sm.rkS[jb][(kf << 3) + lr + 4];
            }
            acc += __shfl_xor_sync(0xffffffffu, acc, 1);
            acc += __shfl_xor_sync(0xffffffffu, acc, 2);
            if (lr == 0) sm.qrelS[rloc][jb] = acc;
        }
    }
    __syncthreads();

    float O0[8][4] = {}, O1[8][4] = {};
    float mS[4], lS[4], bsS[4][NB_] = {};
    #pragma unroll
    for (int st = 0; st < 4; st++) { mS[st] = -1e30f; lS[st] = 0.f; }
    const int rmin = q0 + rw;

    for (int kt = 0; kt < S_ / 32; kt++) {
        const int k0 = kt << 5;
        const int cur = kt & 1;
        CP_WAIT0();
        __syncthreads();
        if (kt + 1 < S_ / 32) { load_kv(cur ^ 1, k0 + 32); CP_COMMIT(); }

        const float (*Kc)[68] = sm.Ks[cur];
        const float (*Vc)[72] = sm.Vs[cur];

        float s0[4][4] = {}, s1[4][4] = {};
        #pragma unroll
        for (int kf = 0; kf < 8; kf++) {
            #pragma unroll
            for (int nf = 0; nf < 4; nf++) {
                float b0 = Kc[(nf << 3) + qd][(kf << 3) + lr];
                float b1 = Kc[(nf << 3) + qd][(kf << 3) + lr + 4];
                mma8f(s0[nf], qf[0][kf], b0, b1);
                mma8f(s1[nf], qf[1][kf], b0, b1);
            }
        }

        bool mixed = (k0 > rmin - 34) && (k0 < rmin + 34);

        #pragma unroll
        for (int h = 0; h < 2; h++) {
            float (*s)[4] = (h == 0) ? s0 : s1;
            int stA = h << 1, stB = stA + 1;
            int rlA = rw + (h << 4) + qd;
            int rgA = q0 + rlA, rgB = rgA + 8;
            float rsA = 0.f, rsB = 0.f;

            if (!mixed) {
                const int bkt = (k0 >= rmin + 34) ? 4 : 0;
                float qbA = sm.qrelS[rlA][bkt] * ALPHA_;
                float qbB = sm.qrelS[rlA + 8][bkt] * ALPHA_;
                float mxA = -1e30f, mxB = -1e30f;
                #pragma unroll
                for (int nf = 0; nf < 4; nf++) {
                    mxA = fmaxf(mxA, fmaxf(s[nf][0], s[nf][1]));
                    mxB = fmaxf(mxB, fmaxf(s[nf][2], s[nf][3]));
                }
                mxA = fmaxf(mxA, __shfl_xor_sync(0xffffffffu, mxA, 1));
                mxA = fmaxf(mxA, __shfl_xor_sync(0xffffffffu, mxA, 2));
                mxB = fmaxf(mxB, __shfl_xor_sync(0xffffffffu, mxB, 1));
                mxB = fmaxf(mxB, __shfl_xor_sync(0xffffffffu, mxB, 2));
                float mnA = fmaxf(mS[stA], fmaf(mxA, ALPHA_, qbA));
                float mnB = fmaxf(mS[stB], fmaf(mxB, ALPHA_, qbB));
                if (__any_sync(0xffffffffu, (mnA > mS[stA]) | (mnB > mS[stB]))) {
                    float scA = exp2p(mS[stA] - mnA), scB = exp2p(mS[stB] - mnB);
                    lS[stA] *= scA; lS[stB] *= scB;
                    #pragma unroll
                    for (int jb = 0; jb < NB_; jb++) { bsS[stA][jb] *= scA; bsS[stB][jb] *= scB; }
                    float (*Oh)[4] = (h == 0) ? O0 : O1;
                    #pragma unroll
                    for (int nf = 0; nf < 8; nf++) {
                        Oh[nf][0] *= scA; Oh[nf][1] *= scA;
                        Oh[nf][2] *= scB; Oh[nf][3] *= scB;
                    }
                }
                mS[stA] = mnA; mS[stB] = mnB;
                float cA = qbA - mnA, cB = qbB - mnB;
                #pragma unroll
                for (int nf = 0; nf < 4; nf++) {
                    float p0 = exp2p(fmaf(s[nf][0], ALPHA_, cA));
                    float p1 = exp2p(fmaf(s[nf][1], ALPHA_, cA));
                    float p2 = exp2p(fmaf(s[nf][2], ALPHA_, cB));
                    float p3 = exp2p(fmaf(s[nf][3], ALPHA_, cB));
                    s[nf][0] = p0; s[nf][1] = p1; s[nf][2] = p2; s[nf][3] = p3;
                    rsA += p0 + p1; rsB += p2 + p3;
                }
                lS[stA] += rsA; lS[stB] += rsB;
                bsS[stA][bkt] += rsA; bsS[stB][bkt] += rsB;
            } else {
                float mxA = -1e30f, mxB = -1e30f;
                int jbs[4][4];
                #pragma unroll
                for (int nf = 0; nf < 4; nf++) {
                    #pragma unroll
                    for (int e = 0; e < 4; e++) {
                        int kp = k0 + (nf << 3) + (lr << 1) + (e & 1);
                        int rg = (e < 2) ? rgA : rgB;
                        int rl = (e < 2) ? rlA : rlA + 8;
                        int jb = min(max(kp - rg, -2), 2) + 2;
                        jbs[nf][e] = jb;
                        float y = (s[nf][e] + sm.qrelS[rl][jb]) * ALPHA_;
                        s[nf][e] = y;
                        if (e < 2) mxA = fmaxf(mxA, y); else mxB = fmaxf(mxB, y);
                    }
                }
                mxA = fmaxf(mxA, __shfl_xor_sync(0xffffffffu, mxA, 1));
                mxA = fmaxf(mxA, __shfl_xor_sync(0xffffffffu, mxA, 2));
                mxB = fmaxf(mxB, __shfl_xor_sync(0xffffffffu, mxB, 1));
                mxB = fmaxf(mxB, __shfl_xor_sync(0xffffffffu, mxB, 2));
                float mnA = fmaxf(mS[stA], mxA);
                float mnB = fmaxf(mS[stB], mxB);
                float scA = exp2p(mS[stA] - mnA), scB = exp2p(mS[stB] - mnB);
                mS[stA] = mnA; mS[stB] = mnB;
                lS[stA] *= scA; lS[stB] *= scB;
                #pragma unroll
                for (int jb = 0; jb < NB_; jb++) { bsS[stA][jb] *= scA; bsS[stB][jb] *= scB; }
                float (*Oh)[4] = (h == 0) ? O0 : O1;
                #pragma unroll
                for (int nf = 0; nf < 8; nf++) {
                    Oh[nf][0] *= scA; Oh[nf][1] *= scA;
                    Oh[nf][2] *= scB; Oh[nf][3] *= scB;
                }
                #pragma unroll
                for (int nf = 0; nf < 4; nf++) {
                    #pragma unroll
                    for (int e = 0; e < 4; e++) {
                        float p = exp2p(s[nf][e] - ((e < 2) ? mnA : mnB));
                        s[nf][e] = p;
                        if (e < 2) { rsA += p; bsS[stA][jbs[nf][e]] += p; }
                        else       { rsB += p; bsS[stB][jbs[nf][e]] += p; }
                    }
                }
                lS[stA] += rsA; lS[stB] += rsB;
            }
        }

        #pragma unroll
        for (int j = 0; j < 4; j++) {
            float a0[4], a1[4];
            {
                float c0 = f2tff(s0[j][0]), c1 = f2tff(s0[j][1]);
                float c2 = f2tff(s0[j][2]), c3 = f2tff(s0[j][3]);
                float t00 = __shfl_sync(0xffffffffu, c0, src0);
                float t10 = __shfl_sync(0xffffffffu, c1, src0);
                float t20 = __shfl_sync(0xffffffffu, c2, src0);
                float t30 = __shfl_sync(0xffffffffu, c3, src0);
                float t01 = __shfl_sync(0xffffffffu, c0, src1);
                float t11 = __shfl_sync(0xffffffffu, c1, src1);
                float t21 = __shfl_sync(0xffffffffu, c2, src1);
                float t31 = __shfl_sync(0xffffffffu, c3, src1);
                a0[0] = odd ? t10 : t00; a0[1] = odd ? t30 : t20;
                a0[2] = odd ? t11 : t01; a0[3] = odd ? t31 : t21;
            }
            {
                float c0 = f2tff(s1[j][0]), c1 = f2tff(s1[j][1]);
                float c2 = f2tff(s1[j][2]), c3 = f2tff(s1[j][3]);
                float t00 = __shfl_sync(0xffffffffu, c0, src0);
                float t10 = __shfl_sync(0xffffffffu, c1, src0);
                float t20 = __shfl_sync(0xffffffffu, c2, src0);
                float t30 = __shfl_sync(0xffffffffu, c3, src0);
                float t01 = __shfl_sync(0xffffffffu, c0, src1);
                float t11 = __shfl_sync(0xffffffffu, c1, src1);
                float t21 = __shfl_sync(0xffffffffu, c2, src1);
                float t31 = __shfl_sync(0xffffffffu, c3, src1);
                a1[0] = odd ? t10 : t00; a1[1] = odd ? t30 : t20;
                a1[2] = odd ? t11 : t01; a1[3] = odd ? t31 : t21;
            }
            #pragma unroll
            for (int nf = 0; nf < 8; nf++) {
                float b0 = Vc[(j << 3) + lr][(nf << 3) + qd];
                float b1 = Vc[(j << 3) + lr + 4][(nf << 3) + qd];
                mma8f(O0[nf], a0, b0, b1);
                mma8f(O1[nf], a1, b0, b1);
            }
        }
    }

    #pragma unroll
    for (int st = 0; st < 4; st++) {
        #pragma unroll
        for (int o = 1; o <= 2; o <<= 1) {
            lS[st] += __shfl_xor_sync(0xffffffffu, lS[st], o);
            #pragma unroll
            for (int jb = 0; jb < NB_; jb++)
                bsS[st][jb] += __shfl_xor_sync(0xffffffffu, bsS[st][jb], o);
        }
    }

    const int bb = bh / H_, hh = bh % H_;
    #pragma unroll
    for (int h = 0; h < 2; h++) {
        float (*Oh)[4] = (h == 0) ? O0 : O1;
        #pragma unroll
        for (int rp = 0; rp < 2; rp++) {
            int st = (h << 1) + rp;
            float inv = 1.f / lS[st];
            int rg = q0 + rw + (h << 4) + qd + (rp << 3);
            #pragma unroll
            for (int nf = 0; nf < 8; nf++) {
                int d0 = (nf << 3) + (lr << 1);
                float o2a = 0.f, o2b = 0.f;
                #pragma unroll
                for (int jb = 0; jb < NB_; jb++) {
                    o2a += bsS[st][jb] * sm.rvS[jb][d0];
                    o2b += bsS[st][jb] * sm.rvS[jb][d0 + 1];
                }
                float2 w = make_float2(f2tff((Oh[nf][(rp << 1)] + o2a) * inv),
                                       f2tff((Oh[nf][(rp << 1) + 1] + o2b) * inv));
                *(float2*)&g_att[(((size_t)bb * S_ + rg) * H_ + hh) * D_ + d0] = w;
            }
        }
    }
}

// ---------------------------------------------------------------------------
extern "C" void kernel_launch(void* const* d_in, const int* in_sizes, int n_in,
                              void* d_out, int out_size) {
    const float* x    = (const float*)d_in[0];
    const float* Wq   = (const float*)d_in[1];
    const float* bq   = (const float*)d_in[2];
    const float* Wk   = (const float*)d_in[3];
    const float* bk   = (const float*)d_in[4];
    const float* Wv   = (const float*)d_in[5];
    const float* bv   = (const float*)d_in[6];
    const float* Wo   = (const float*)d_in[7];
    const float* bo   = (const float*)d_in[8];
    const float* relk = (const float*)d_in[9];
    const float* relv = (const float*)d_in[10];
    float* out = (float*)d_out;

    float *gq, *gk, *gv, *gatt, *gxr;
    cudaGetSymbolAddress((void**)&gq,   g_q);
    cudaGetSymbolAddress((void**)&gk,   g_k);
    cudaGetSymbolAddress((void**)&gv,   g_v);
    cudaGetSymbolAddress((void**)&gatt, g_att);
    cudaGetSymbolAddress((void**)&gxr,  g_xr);

    cudaFuncSetAttribute(gemm_qkv, cudaFuncAttributeMaxDynamicSharedMemorySize,
                         (int)sizeof(GSmem));
    cudaFuncSetAttribute(gemm_out, cudaFuncAttributeMaxDynamicSharedMemorySize,
                         (int)sizeof(GSmem));
    cudaFuncSetAttribute(attn_tf32, cudaFuncAttributeMaxDynamicSharedMemorySize,
                         (int)sizeof(ASmem));

    round_x<<<1024, 256>>>(x);
    transpose_w<<<dim3(32, 32, 4), dim3(32, 8)>>>(Wq, Wk, Wv, Wo);

    gemm_qkv<<<dim3(DM_ / 64, (B_ * S_) / 128, 3), 256, sizeof(GSmem)>>>(
        gxr, bq, bk, bv, gq, gk, gv);
    attn_tf32<<<dim3(S_ / 128, B_ * H_), 128, sizeof(ASmem)>>>(relk, relv);
    gemm_out<<<dim3(DM_ / 64, (B_ * S_) / 128), 256, sizeof(GSmem)>>>(gatt, bo, out);
}

// round 11
// speedup vs baseline: 1.1486x; 1.1486x over previous
#include <cuda_runtime.h>
#include <cstdint>

#define B_   2
#define S_   2048
#define DM_  1024
#define H_   16
#define D_   64
#define NB_  5
#define SCALE_ 0.125f
#define LOG2E_ 1.4426950408889634f
#define ALPHA_ (SCALE_ * LOG2E_)

// Static device scratch
__device__ float g_q[B_*H_*S_*D_];
__device__ float g_k[B_*H_*S_*D_];
__device__ float g_v[B_*H_*S_*D_];
__device__ float g_att[B_*S_*DM_];
__device__ float g_xr[4096*1024];
__device__ float g_wr[4][1024*1024];   // tf32-rounded W (k-major, straight)

// ---------------------------------------------------------------------------
__device__ __forceinline__ unsigned f2tf(float x) {
    unsigned r;
    asm("cvt.rna.tf32.f32 %0, %1;" : "=r"(r) : "f"(x));
    return r;
}
__device__ __forceinline__ float f2tff(float x) { return __uint_as_float(f2tf(x)); }

__device__ __forceinline__ void mma8f(float* c, const float* a, float b0f, float b1f) {
    asm volatile(
        "mma.sync.aligned.m16n8k8.row.col.f32.tf32.tf32.f32 "
        "{%0,%1,%2,%3}, {%4,%5,%6,%7}, {%8,%9}, {%0,%1,%2,%3};"
        : "+f"(c[0]), "+f"(c[1]), "+f"(c[2]), "+f"(c[3])
        : "r"(__float_as_uint(a[0])), "r"(__float_as_uint(a[1])),
          "r"(__float_as_uint(a[2])), "r"(__float_as_uint(a[3])),
          "r"(__float_as_uint(b0f)), "r"(__float_as_uint(b1f)));
}

#define CP16(dst_smem, src) \
    asm volatile("cp.async.cg.shared.global [%0], [%1], 16;\n" :: \
        "r"((unsigned)__cvta_generic_to_shared(dst_smem)), "l"(src) : "memory")
#define CP_COMMIT() asm volatile("cp.async.commit_group;\n" ::: "memory")
#define CP_WAIT0()  asm volatile("cp.async.wait_group 0;\n" ::: "memory")
#define CP_WAIT1()  asm volatile("cp.async.wait_group 1;\n" ::: "memory")

// exp2 on FMA pipe, no max subtraction needed: valid for |y| < ~2^22,
// clamps low at -60 (2^-60 mass is negligible vs l).
__device__ __forceinline__ float exp2p(float y) {
    y = fmaxf(y, -60.f);
    float t = y + 12582912.0f;           // 1.5*2^23 round-to-nearest
    float fl = t - 12582912.0f;
    float f = y - fl;                    // [-0.5, 0.5]
    float p = fmaf(1.5403530e-4f, f, 1.3333558e-3f);
    p = fmaf(p, f, 9.6181291e-3f);
    p = fmaf(p, f, 5.5504109e-2f);
    p = fmaf(p, f, 2.4022651e-1f);
    p = fmaf(p, f, 6.9314718e-1f);
    p = fmaf(p, f, 1.0f);
    int e = ((__float_as_int(t) & 0x7FFFFF) - 0x400000 + 127) << 23;
    return p * __int_as_float(e);
}

// ---------------------------------------------------------------------------
// Pre-pass: tf32-round x and the 4 weight matrices (straight layout).
// ---------------------------------------------------------------------------
__global__ void round_pass(const float* __restrict__ x,  const float* __restrict__ wq,
                           const float* __restrict__ wk, const float* __restrict__ wv,
                           const float* __restrict__ wo)
{
    const int total = 1048576 + 4 * 262144;
    for (int i = blockIdx.x * blockDim.x + threadIdx.x; i < total;
         i += gridDim.x * blockDim.x) {
        const float4* src; float4* dst; int off;
        if (i < 1048576) { src = (const float4*)x; dst = (float4*)g_xr; off = i; }
        else {
            int j = i - 1048576; int seg = j >> 18; off = j & 262143;
            const float* s4 = (seg == 0) ? wq : (seg == 1) ? wk : (seg == 2) ? wv : wo;
            src = (const float4*)s4; dst = (float4*)g_wr[seg];
        }
        float4 v = src[off];
        v.x = f2tff(v.x); v.y = f2tff(v.y); v.z = f2tff(v.z); v.w = f2tff(v.w);
        dst[off] = v;
    }
}

// ---------------------------------------------------------------------------
// TF32 GEMM (R7 config): 128x128 tile, 256 thr, k-step 32, 3-stage cp.async.
// Single barrier per k-iter (3-stage ring makes the trailing sync redundant).
// ---------------------------------------------------------------------------
struct GSmem {
    float Xs[3][128][36];
    float Ws[3][32][132];
};

__device__ __forceinline__ void gemm_body(
    GSmem& sm, const float* __restrict__ X, const float* __restrict__ W,
    const float* __restrict__ bias, float* __restrict__ out, int permute,
    int m0, int n0)
{
    const int tid  = threadIdx.x;
    const int lane = tid & 31, wid = tid >> 5;
    const int qd = lane >> 2, lr = lane & 3;
    const int wm = wid >> 2, wn = wid & 3;

    const int xr = tid >> 3, xc = (tid & 7) << 2;
    const int wr = tid >> 5, wc = (tid & 31) << 2;

    auto load_tile = [&](int buf, int k0) {
        #pragma unroll
        for (int it = 0; it < 4; it++)
            CP16(&sm.Xs[buf][xr + (it << 5)][xc],
                 &X[(size_t)(m0 + xr + (it << 5)) * DM_ + k0 + xc]);
        #pragma unroll
        for (int it = 0; it < 4; it++)
            CP16(&sm.Ws[buf][wr + (it << 3)][wc],
                 &W[(size_t)(k0 + wr + (it << 3)) * DM_ + n0 + wc]);
    };

    load_tile(0, 0);  CP_COMMIT();
    load_tile(1, 32); CP_COMMIT();

    float acc[4][4][4] = {};
    int buf = 0;

    for (int kt = 0; kt < DM_ / 32; kt++) {
        CP_WAIT1();
        __syncthreads();
        if (kt + 2 < DM_ / 32) {
            int nb = buf + 2; if (nb >= 3) nb -= 3;
            load_tile(nb, (kt + 2) << 5);
            CP_COMMIT();
        }

        #pragma unroll
        for (int ks = 0; ks < 4; ks++) {
            int kk = ks << 3;
            float a[4][4], b[4][2];
            #pragma unroll
            for (int mf = 0; mf < 4; mf++) {
                int r = (wm << 6) + (mf << 4) + qd;
                a[mf][0] = sm.Xs[buf][r][kk + lr];
                a[mf][1] = sm.Xs[buf][r + 8][kk + lr];
                a[mf][2] = sm.Xs[buf][r][kk + lr + 4];
                a[mf][3] = sm.Xs[buf][r + 8][kk + lr + 4];
            }
            #pragma unroll
            for (int nf = 0; nf < 4; nf++) {
                int n = (wn << 5) + (nf << 3) + qd;
                b[nf][0] = sm.Ws[buf][kk + lr][n];
                b[nf][1] = sm.Ws[buf][kk + lr + 4][n];
            }
            #pragma unroll
            for (int mf = 0; mf < 4; mf++)
                #pragma unroll
                for (int nf = 0; nf < 4; nf++)
                    mma8f(acc[mf][nf], a[mf], b[nf][0], b[nf][1]);
        }
        if (++buf >= 3) buf -= 3;
    }

    #pragma unroll
    for (int mf = 0; mf < 4; mf++) {
        #pragma unroll
        for (int nf = 0; nf < 4; nf++) {
            #pragma unroll
            for (int rp = 0; rp < 2; rp++) {
                int m = m0 + (wm << 6) + (mf << 4) + qd + (rp << 3);
                int n = n0 + (wn << 5) + (nf << 3) + (lr << 1);
                float v0 = acc[mf][nf][(rp << 1)]     + __ldg(&bias[n]);
                float v1 = acc[mf][nf][(rp << 1) + 1] + __ldg(&bias[n + 1]);
                if (permute) {
                    int bb = m >> 11, s = m & (S_ - 1);
                    int h = n >> 6, d = n & 63;
                    float2 w = make_float2(f2tff(v0), f2tff(v1));
                    *(float2*)&out[(((bb * H_ + h) * S_) + s) * D_ + d] = w;
                } else {
                    *(float2*)&out[(size_t)m * DM_ + n] = make_float2(v0, v1);
                }
            }
        }
    }
}

__global__ __launch_bounds__(256) void gemm_qkv(
    const float* __restrict__ X,
    const float* __restrict__ b0, const float* __restrict__ b1, const float* __restrict__ b2,
    float* __restrict__ o0, float* __restrict__ o1, float* __restrict__ o2)
{
    extern __shared__ char graw[];
    GSmem& sm = *reinterpret_cast<GSmem*>(graw);
    const int z = blockIdx.z;
    const float* bias = (z == 0) ? b0 : (z == 1) ? b1 : b2;
    float* out = (z == 0) ? o0 : (z == 1) ? o1 : o2;
    gemm_body(sm, X, g_wr[z], bias, out, 1, blockIdx.y << 7, blockIdx.x << 7);
}

__global__ __launch_bounds__(256) void gemm_out(
    const float* __restrict__ X, const float* __restrict__ bias, float* __restrict__ out)
{
    extern __shared__ char graw[];
    GSmem& sm = *reinterpret_cast<GSmem*>(graw);
    gemm_body(sm, X, g_wr[3], bias, out, 0, blockIdx.y << 7, blockIdx.x << 7);
}

// ---------------------------------------------------------------------------
// Flash attention, MAX-FREE softmax (scores bounded -> direct exp, purely
// additive partial sums; normalize once at the end). q-tile 128, m32/warp,
// k-tile 32, cp.async DB, register shuffle-transpose for P.
// ---------------------------------------------------------------------------
struct ASmem {
    float Ks[2][32][68];
    float Vs[2][32][72];
    float qrelS[128][8];
    float rkS[NB_][64];
    float rvS[NB_][64];
};

__global__ __launch_bounds__(128, 2) void attn_tf32(
    const float* __restrict__ rel_k, const float* __restrict__ rel_v)
{
    extern __shared__ char sraw[];
    ASmem& sm = *reinterpret_cast<ASmem*>(sraw);
    const int tid = threadIdx.x;
    const int lane = tid & 31, wid = tid >> 5;
    const int qd = lane >> 2, lr = lane & 3;
    const bool odd = lr & 1;
    const int src0 = (lane & 28) | (lr >> 1);
    const int src1 = src0 + 2;
    const int q0 = blockIdx.x << 7;
    const int bh = blockIdx.y;
    const float* qptr = g_q + (size_t)bh * S_ * D_;
    const float* kptr = g_k + (size_t)bh * S_ * D_;
    const float* vptr = g_v + (size_t)bh * S_ * D_;

    auto load_kv = [&](int buf, int k0) {
        #pragma unroll
        for (int it = 0; it < 4; it++) {
            int idx = tid + (it << 7);
            int r = idx >> 4, c4 = (idx & 15) << 2;
            CP16(&sm.Ks[buf][r][c4], &kptr[(size_t)(k0 + r) * D_ + c4]);
            CP16(&sm.Vs[buf][r][c4], &vptr[(size_t)(k0 + r) * D_ + c4]);
        }
    };

    load_kv(0, 0);
    CP_COMMIT();

    for (int t = tid; t < NB_ * 64; t += 128) {
        sm.rkS[t >> 6][t & 63] = rel_k[t];
        sm.rvS[t >> 6][t & 63] = rel_v[t];
    }

    // Q fragments straight from gmem (pre-rounded tf32)
    const int rw = wid << 5;
    float qf[2][8][4];
    #pragma unroll
    for (int h = 0; h < 2; h++) {
        const float* qr0 = &qptr[(size_t)(q0 + rw + (h << 4) + qd) * D_];
        #pragma unroll
        for (int kf = 0; kf < 8; kf++) {
            qf[h][kf][0] = __ldg(&qr0[(kf << 3) + lr]);
            qf[h][kf][1] = __ldg(&qr0[(size_t)8 * D_ + (kf << 3) + lr]);
            qf[h][kf][2] = __ldg(&qr0[(kf << 3) + lr + 4]);
            qf[h][kf][3] = __ldg(&qr0[(size_t)8 * D_ + (kf << 3) + lr + 4]);
        }
    }
    __syncthreads();

    // qrel[r][jb] from register Q frags
    #pragma unroll
    for (int st = 0; st < 4; st++) {
        int h = st >> 1, rp = st & 1;
        int rloc = rw + (h << 4) + qd + (rp << 3);
        #pragma unroll
        for (int jb = 0; jb < NB_; jb++) {
            float acc = 0.f;
            #pragma unroll
            for (int kf = 0; kf < 8; kf++) {
                acc += qf[h][kf][rp]     * sm.rkS[jb][(kf << 3) + lr];
                acc += qf[h][kf][rp + 2] * sm.rkS[jb][(kf << 3) + lr + 4];
            }
            acc += __shfl_xor_sync(0xffffffffu, acc, 1);
            acc += __shfl_xor_sync(0xffffffffu, acc, 2);
            if (lr == 0) sm.qrelS[rloc][jb] = acc;
        }
    }
    __syncthreads();

    float O0[8][4] = {}, O1[8][4] = {};
    float lS[4] = {}, bsS[4][NB_] = {};
    const int rmin = q0 + rw;

    for (int kt = 0; kt < S_ / 32; kt++) {
        const int k0 = kt << 5;
        const int cur = kt & 1;
        CP_WAIT0();
        __syncthreads();
        if (kt + 1 < S_ / 32) { load_kv(cur ^ 1, k0 + 32); CP_COMMIT(); }

        const float (*Kc)[68] = sm.Ks[cur];
        const float (*Vc)[72] = sm.Vs[cur];

        // S = Q @ K^T for both halves, shared B fragments
        float s0[4][4] = {}, s1[4][4] = {};
        #pragma unroll
        for (int kf = 0; kf < 8; kf++) {
            #pragma unroll
            for (int nf = 0; nf < 4; nf++) {
                float b0 = Kc[(nf << 3) + qd][(kf << 3) + lr];
                float b1 = Kc[(nf << 3) + qd][(kf << 3) + lr + 4];
                mma8f(s0[nf], qf[0][kf], b0, b1);
                mma8f(s1[nf], qf[1][kf], b0, b1);
            }
        }

        bool mixed = (k0 > rmin - 34) && (k0 < rmin + 34);

        // Max-free softmax accumulation
        #pragma unroll
        for (int h = 0; h < 2; h++) {
            float (*s)[4] = (h == 0) ? s0 : s1;
            int stA = h << 1, stB = stA + 1;
            int rlA = rw + (h << 4) + qd;
            int rgA = q0 + rlA, rgB = rgA + 8;
            float rsA = 0.f, rsB = 0.f;

            if (!mixed) {
                const int bkt = (k0 >= rmin + 34) ? 4 : 0;
                float cA = sm.qrelS[rlA][bkt] * ALPHA_;
                float cB = sm.qrelS[rlA + 8][bkt] * ALPHA_;
                #pragma unroll
                for (int nf = 0; nf < 4; nf++) {
                    float p0 = exp2p(fmaf(s[nf][0], ALPHA_, cA));
                    float p1 = exp2p(fmaf(s[nf][1], ALPHA_, cA));
                    float p2 = exp2p(fmaf(s[nf][2], ALPHA_, cB));
                    float p3 = exp2p(fmaf(s[nf][3], ALPHA_, cB));
                    s[nf][0] = p0; s[nf][1] = p1; s[nf][2] = p2; s[nf][3] = p3;
                    rsA += p0 + p1; rsB += p2 + p3;
                }
                lS[stA] += rsA; lS[stB] += rsB;
                bsS[stA][bkt] += rsA; bsS[stB][bkt] += rsB;
            } else {
                #pragma unroll
                for (int nf = 0; nf < 4; nf++) {
                    #pragma unroll
                    for (int e = 0; e < 4; e++) {
                        int kp = k0 + (nf << 3) + (lr << 1) + (e & 1);
                        int rg = (e < 2) ? rgA : rgB;
                        int rl = (e < 2) ? rlA : rlA + 8;
                        int jb = min(max(kp - rg, -2), 2) + 2;
                        float p = exp2p((s[nf][e] + sm.qrelS[rl][jb]) * ALPHA_);
                        s[nf][e] = p;
                        if (e < 2) { rsA += p; bsS[stA][jb] += p; }
                        else       { rsB += p; bsS[stB][jb] += p; }
                    }
                }
                lS[stA] += rsA; lS[stB] += rsB;
            }
        }

        // O += P @ V. P C-layout -> A-layout via quad shuffles, V B-frags shared.
        #pragma unroll
        for (int j = 0; j < 4; j++) {
            float a0[4], a1[4];
            {
                float c0 = f2tff(s0[j][0]), c1 = f2tff(s0[j][1]);
                float c2 = f2tff(s0[j][2]), c3 = f2tff(s0[j][3]);
                float t00 = __shfl_sync(0xffffffffu, c0, src0);
                float t10 = __shfl_sync(0xffffffffu, c1, src0);
                float t20 = __shfl_sync(0xffffffffu, c2, src0);
                float t30 = __shfl_sync(0xffffffffu, c3, src0);
                float t01 = __shfl_sync(0xffffffffu, c0, src1);
                float t11 = __shfl_sync(0xffffffffu, c1, src1);
                float t21 = __shfl_sync(0xffffffffu, c2, src1);
                float t31 = __shfl_sync(0xffffffffu, c3, src1);
                a0[0] = odd ? t10 : t00; a0[1] = odd ? t30 : t20;
                a0[2] = odd ? t11 : t01; a0[3] = odd ? t31 : t21;
            }
            {
                float c0 = f2tff(s1[j][0]), c1 = f2tff(s1[j][1]);
                float c2 = f2tff(s1[j][2]), c3 = f2tff(s1[j][3]);
                float t00 = __shfl_sync(0xffffffffu, c0, src0);
                float t10 = __shfl_sync(0xffffffffu, c1, src0);
                float t20 = __shfl_sync(0xffffffffu, c2, src0);
                float t30 = __shfl_sync(0xffffffffu, c3, src0);
                float t01 = __shfl_sync(0xffffffffu, c0, src1);
                float t11 = __shfl_sync(0xffffffffu, c1, src1);
                float t21 = __shfl_sync(0xffffffffu, c2, src1);
                float t31 = __shfl_sync(0xffffffffu, c3, src1);
                a1[0] = odd ? t10 : t00; a1[1] = odd ? t30 : t20;
                a1[2] = odd ? t11 : t01; a1[3] = odd ? t31 : t21;
            }
            #pragma unroll
            for (int nf = 0; nf < 8; nf++) {
                float b0 = Vc[(j << 3) + lr][(nf << 3) + qd];
                float b1 = Vc[(j << 3) + lr + 4][(nf << 3) + qd];
                mma8f(O0[nf], a0, b0, b1);
                mma8f(O1[nf], a1, b0, b1);
            }
        }
    }

    // quad reductions of l and bucket sums
    #pragma unroll
    for (int st = 0; st < 4; st++) {
        #pragma unroll
        for (int o = 1; o <= 2; o <<= 1) {
            lS[st] += __shfl_xor_sync(0xffffffffu, lS[st], o);
            #pragma unroll
            for (int jb = 0; jb < NB_; jb++)
                bsS[st][jb] += __shfl_xor_sync(0xffffffffu, bsS[st][jb], o);
        }
    }

    const int bb = bh / H_, hh = bh % H_;
    #pragma unroll
    for (int h = 0; h < 2; h++) {
        float (*Oh)[4] = (h == 0) ? O0 : O1;
        #pragma unroll
        for (int rp = 0; rp < 2; rp++) {
            int st = (h << 1) + rp;
            float inv = 1.f / lS[st];
            int rg = q0 + rw + (h << 4) + qd + (rp << 3);
            #pragma unroll
            for (int nf = 0; nf < 8; nf++) {
                int d0 = (nf << 3) + (lr << 1);
                float o2a = 0.f, o2b = 0.f;
                #pragma unroll
                for (int jb = 0; jb < NB_; jb++) {
                    o2a += bsS[st][jb] * sm.rvS[jb][d0];
                    o2b += bsS[st][jb] * sm.rvS[jb][d0 + 1];
                }
                float2 w = make_float2(f2tff((Oh[nf][(rp << 1)] + o2a) * inv),
                                       f2tff((Oh[nf][(rp << 1) + 1] + o2b) * inv));
                *(float2*)&g_att[(((size_t)bb * S_ + rg) * H_ + hh) * D_ + d0] = w;
            }
        }
    }
}

// ---------------------------------------------------------------------------
extern "C" void kernel_launch(void* const* d_in, const int* in_sizes, int n_in,
                              void* d_out, int out_size) {
    const float* x    = (const float*)d_in[0];
    const float* Wq   = (const float*)d_in[1];
    const float* bq   = (const float*)d_in[2];
    const float* Wk   = (const float*)d_in[3];
    const float* bk   = (const float*)d_in[4];
    const float* Wv   = (const float*)d_in[5];
    const float* bv   = (const float*)d_in[6];
    const float* Wo   = (const float*)d_in[7];
    const float* bo   = (const float*)d_in[8];
    const float* relk = (const float*)d_in[9];
    const float* relv = (const float*)d_in[10];
    float* out = (float*)d_out;

    float *gq, *gk, *gv, *gatt, *gxr;
    cudaGetSymbolAddress((void**)&gq,   g_q);
    cudaGetSymbolAddress((void**)&gk,   g_k);
    cudaGetSymbolAddress((void**)&gv,   g_v);
    cudaGetSymbolAddress((void**)&gatt, g_att);
    cudaGetSymbolAddress((void**)&gxr,  g_xr);

    cudaFuncSetAttribute(gemm_qkv, cudaFuncAttributeMaxDynamicSharedMemorySize,
                         (int)sizeof(GSmem));
    cudaFuncSetAttribute(gemm_out, cudaFuncAttributeMaxDynamicSharedMemorySize,
                         (int)sizeof(GSmem));
    cudaFuncSetAttribute(attn_tf32, cudaFuncAttributeMaxDynamicSharedMemorySize,
                         (int)sizeof(ASmem));

    round_pass<<<2048, 256>>>(x, Wq, Wk, Wv, Wo);

    gemm_qkv<<<dim3(DM_ / 128, (B_ * S_) / 128, 3), 256, sizeof(GSmem)>>>(
        gxr, bq, bk, bv, gq, gk, gv);
    attn_tf32<<<dim3(S_ / 128, B_ * H_), 128, sizeof(ASmem)>>>(relk, relv);
    gemm_out<<<dim3(DM_ / 128, (B_ * S_) / 128), 256, sizeof(GSmem)>>>(gatt, bo, out);
}

// round 14
// speedup vs baseline: 1.1874x; 1.0338x over previous
#include <cuda_runtime.h>
#include <cstdint>

#define B_   2
#define S_   2048
#define DM_  1024
#define H_   16
#define D_   64
#define NB_  5
#define SCALE_ 0.125f
#define LOG2E_ 1.4426950408889634f
#define ALPHA_ (SCALE_ * LOG2E_)

// Static device scratch
__device__ float g_q[B_*H_*S_*D_];
__device__ float g_k[B_*H_*S_*D_];
__device__ float g_v[B_*H_*S_*D_];
__device__ float g_att[B_*S_*DM_];
__device__ float g_xr[4096*1024];
__device__ float g_wr[4][1024*1024];   // tf32-rounded W (k-major, straight)

// ---------------------------------------------------------------------------
__device__ __forceinline__ unsigned f2tf(float x) {
    unsigned r;
    asm("cvt.rna.tf32.f32 %0, %1;" : "=r"(r) : "f"(x));
    return r;
}
__device__ __forceinline__ float f2tff(float x) { return __uint_as_float(f2tf(x)); }

__device__ __forceinline__ void mma8f(float* c, const float* a, float b0f, float b1f) {
    asm volatile(
        "mma.sync.aligned.m16n8k8.row.col.f32.tf32.tf32.f32 "
        "{%0,%1,%2,%3}, {%4,%5,%6,%7}, {%8,%9}, {%0,%1,%2,%3};"
        : "+f"(c[0]), "+f"(c[1]), "+f"(c[2]), "+f"(c[3])
        : "r"(__float_as_uint(a[0])), "r"(__float_as_uint(a[1])),
          "r"(__float_as_uint(a[2])), "r"(__float_as_uint(a[3])),
          "r"(__float_as_uint(b0f)), "r"(__float_as_uint(b1f)));
}

#define CP16(dst_smem, src) \
    asm volatile("cp.async.cg.shared.global [%0], [%1], 16;\n" :: \
        "r"((unsigned)__cvta_generic_to_shared(dst_smem)), "l"(src) : "memory")
#define CP_COMMIT() asm volatile("cp.async.commit_group;\n" ::: "memory")
#define CP_WAIT0()  asm volatile("cp.async.wait_group 0;\n" ::: "memory")
#define CP_WAIT1()  asm volatile("cp.async.wait_group 1;\n" ::: "memory")

// exp2 on FMA pipe, max-free softmax domain; clamps low at -60.
__device__ __forceinline__ float exp2p(float y) {
    y = fmaxf(y, -60.f);
    float t = y + 12582912.0f;           // 1.5*2^23 round-to-nearest
    float fl = t - 12582912.0f;
    float f = y - fl;                    // [-0.5, 0.5]
    float p = fmaf(1.5403530e-4f, f, 1.3333558e-3f);
    p = fmaf(p, f, 9.6181291e-3f);
    p = fmaf(p, f, 5.5504109e-2f);
    p = fmaf(p, f, 2.4022651e-1f);
    p = fmaf(p, f, 6.9314718e-1f);
    p = fmaf(p, f, 1.0f);
    int e = ((__float_as_int(t) & 0x7FFFFF) - 0x400000 + 127) << 23;
    return p * __int_as_float(e);
}

// ---------------------------------------------------------------------------
// Pre-pass: tf32-round x and the 4 weight matrices.
// ---------------------------------------------------------------------------
__global__ void round_pass(const float* __restrict__ x,  const float* __restrict__ wq,
                           const float* __restrict__ wk, const float* __restrict__ wv,
                           const float* __restrict__ wo)
{
    const int total = 1048576 + 4 * 262144;
    for (int i = blockIdx.x * blockDim.x + threadIdx.x; i < total;
         i += gridDim.x * blockDim.x) {
        const float4* src; float4* dst; int off;
        if (i < 1048576) { src = (const float4*)x; dst = (float4*)g_xr; off = i; }
        else {
            int j = i - 1048576; int seg = j >> 18; off = j & 262143;
            const float* s4 = (seg == 0) ? wq : (seg == 1) ? wk : (seg == 2) ? wv : wo;
            src = (const float4*)s4; dst = (float4*)g_wr[seg];
        }
        float4 v = src[off];
        v.x = f2tff(v.x); v.y = f2tff(v.y); v.z = f2tff(v.z); v.w = f2tff(v.w);
        dst[off] = v;
    }
}

// ---------------------------------------------------------------------------
// TF32 GEMM v3: block 128x128, 128 threads (4 warps, warp tile 64x64),
// k-step 32, 3-stage cp.async. LDS:MMA = 1:1 (vs 1.5:1 with 8-warp config).
// ---------------------------------------------------------------------------
struct GSmem {
    float Xs[3][128][36];
    float Ws[3][32][132];
};

__device__ __forceinline__ void gemm_body(
    GSmem& sm, const float* __restrict__ X, const float* __restrict__ W,
    const float* __restrict__ bias, float* __restrict__ out, int permute,
    int m0, int n0)
{
    const int tid  = threadIdx.x;
    const int lane = tid & 31, wid = tid >> 5;
    const int qd = lane >> 2, lr = lane & 3;
    const int wm = wid >> 1, wn = wid & 1;     // warp grid 2x2, tile 64x64

    const int xr = tid >> 3, xc = (tid & 7) << 2;   // X: 16 rows/iter, 8 iters
    const int wr = tid >> 5, wc = (tid & 31) << 2;  // W: 4 k-rows/iter, 8 iters

    auto load_tile = [&](int buf, int k0) {
        #pragma unroll
        for (int it = 0; it < 8; it++)
            CP16(&sm.Xs[buf][xr + (it << 4)][xc],
                 &X[(size_t)(m0 + xr + (it << 4)) * DM_ + k0 + xc]);
        #pragma unroll
        for (int it = 0; it < 8; it++)
            CP16(&sm.Ws[buf][wr + (it << 2)][wc],
                 &W[(size_t)(k0 + wr + (it << 2)) * DM_ + n0 + wc]);
    };

    load_tile(0, 0);  CP_COMMIT();
    load_tile(1, 32); CP_COMMIT();

    float acc[4][8][4] = {};
    int buf = 0;

    for (int kt = 0; kt < DM_ / 32; kt++) {
        CP_WAIT1();
        __syncthreads();
        if (kt + 2 < DM_ / 32) {
            int nb = buf + 2; if (nb >= 3) nb -= 3;
            load_tile(nb, (kt + 2) << 5);
            CP_COMMIT();
        }

        #pragma unroll
        for (int ks = 0; ks < 4; ks++) {
            int kk = ks << 3;
            float a[4][4], b[8][2];
            #pragma unroll
            for (int mf = 0; mf < 4; mf++) {
                int r = (wm << 6) + (mf << 4) + qd;
                a[mf][0] = sm.Xs[buf][r][kk + lr];
                a[mf][1] = sm.Xs[buf][r + 8][kk + lr];
                a[mf][2] = sm.Xs[buf][r][kk + lr + 4];
                a[mf][3] = sm.Xs[buf][r + 8][kk + lr + 4];
            }
            #pragma unroll
            for (int nf = 0; nf < 8; nf++) {
                int n = (wn << 6) + (nf << 3) + qd;
                b[nf][0] = sm.Ws[buf][kk + lr][n];
                b[nf][1] = sm.Ws[buf][kk + lr + 4][n];
            }
            #pragma unroll
            for (int mf = 0; mf < 4; mf++)
                #pragma unroll
                for (int nf = 0; nf < 8; nf++)
                    mma8f(acc[mf][nf], a[mf], b[nf][0], b[nf][1]);
        }
        if (++buf >= 3) buf -= 3;
    }

    #pragma unroll
    for (int mf = 0; mf < 4; mf++) {
        #pragma unroll
        for (int nf = 0; nf < 8; nf++) {
            #pragma unroll
            for (int rp = 0; rp < 2; rp++) {
                int m = m0 + (wm << 6) + (mf << 4) + qd + (rp << 3);
                int n = n0 + (wn << 6) + (nf << 3) + (lr << 1);
                float v0 = acc[mf][nf][(rp << 1)]     + __ldg(&bias[n]);
                float v1 = acc[mf][nf][(rp << 1) + 1] + __ldg(&bias[n + 1]);
                if (permute) {
                    int bb = m >> 11, s = m & (S_ - 1);
                    int h = n >> 6, d = n & 63;
                    float2 w = make_float2(f2tff(v0), f2tff(v1));
                    *(float2*)&out[(((bb * H_ + h) * S_) + s) * D_ + d] = w;
                } else {
                    *(float2*)&out[(size_t)m * DM_ + n] = make_float2(v0, v1);
                }
            }
        }
    }
}

__global__ __launch_bounds__(128) void gemm_qkv(
    const float* __restrict__ X,
    const float* __restrict__ b0, const float* __restrict__ b1, const float* __restrict__ b2,
    float* __restrict__ o0, float* __restrict__ o1, float* __restrict__ o2)
{
    extern __shared__ char graw[];
    GSmem& sm = *reinterpret_cast<GSmem*>(graw);
    const int z = blockIdx.z;
    const float* bias = (z == 0) ? b0 : (z == 1) ? b1 : b2;
    float* out = (z == 0) ? o0 : (z == 1) ? o1 : o2;
    gemm_body(sm, X, g_wr[z], bias, out, 1, blockIdx.y << 7, blockIdx.x << 7);
}

__global__ __launch_bounds__(128) void gemm_out(
    const float* __restrict__ X, const float* __restrict__ bias, float* __restrict__ out)
{
    extern __shared__ char graw[];
    GSmem& sm = *reinterpret_cast<GSmem*>(graw);
    gemm_body(sm, X, g_wr[3], bias, out, 0, blockIdx.y << 7, blockIdx.x << 7);
}

// ---------------------------------------------------------------------------
// Flash attention (unchanged from R11): max-free softmax, q-tile 128,
// m32/warp, k-tile 32, cp.async DB, register shuffle-transpose for P.
// ---------------------------------------------------------------------------
struct ASmem {
    float Ks[2][32][68];
    float Vs[2][32][72];
    float qrelS[128][8];
    float rkS[NB_][64];
    float rvS[NB_][64];
};

__global__ __launch_bounds__(128, 2) void attn_tf32(
    const float* __restrict__ rel_k, const float* __restrict__ rel_v)
{
    extern __shared__ char sraw[];
    ASmem& sm = *reinterpret_cast<ASmem*>(sraw);
    const int tid = threadIdx.x;
    const int lane = tid & 31, wid = tid >> 5;
    const int qd = lane >> 2, lr = lane & 3;
    const bool odd = lr & 1;
    const int src0 = (lane & 28) | (lr >> 1);
    const int src1 = src0 + 2;
    const int q0 = blockIdx.x << 7;
    const int bh = blockIdx.y;
    const float* qptr = g_q + (size_t)bh * S_ * D_;
    const float* kptr = g_k + (size_t)bh * S_ * D_;
    const float* vptr = g_v + (size_t)bh * S_ * D_;

    auto load_kv = [&](int buf, int k0) {
        #pragma unroll
        for (int it = 0; it < 4; it++) {
            int idx = tid + (it << 7);
            int r = idx >> 4, c4 = (idx & 15) << 2;
            CP16(&sm.Ks[buf][r][c4], &kptr[(size_t)(k0 + r) * D_ + c4]);
            CP16(&sm.Vs[buf][r][c4], &vptr[(size_t)(k0 + r) * D_ + c4]);
        }
    };

    load_kv(0, 0);
    CP_COMMIT();

    for (int t = tid; t < NB_ * 64; t += 128) {
        sm.rkS[t >> 6][t & 63] = rel_k[t];
        sm.rvS[t >> 6][t & 63] = rel_v[t];
    }

    const int rw = wid << 5;
    float qf[2][8][4];
    #pragma unroll
    for (int h = 0; h < 2; h++) {
        const float* qr0 = &qptr[(size_t)(q0 + rw + (h << 4) + qd) * D_];
        #pragma unroll
        for (int kf = 0; kf < 8; kf++) {
            qf[h][kf][0] = __ldg(&qr0[(kf << 3) + lr]);
            qf[h][kf][1] = __ldg(&qr0[(size_t)8 * D_ + (kf << 3) + lr]);
            qf[h][kf][2] = __ldg(&qr0[(kf << 3) + lr + 4]);
            qf[h][kf][3] = __ldg(&qr0[(size_t)8 * D_ + (kf << 3) + lr + 4]);
        }
    }
    __syncthreads();

    #pragma unroll
    for (int st = 0; st < 4; st++) {
        int h = st >> 1, rp = st & 1;
        int rloc = rw + (h << 4) + qd + (rp << 3);
        #pragma unroll
        for (int jb = 0; jb < NB_; jb++) {
            float acc = 0.f;
            #pragma unroll
            for (int kf = 0; kf < 8; kf++) {
                acc += qf[h][kf][rp]     * sm.rkS[jb][(kf << 3) + lr];
                acc += qf[h][kf][rp + 2] * sm.rkS[jb][(kf << 3) + lr + 4];
            }
            acc += __shfl_xor_sync(0xffffffffu, acc, 1);
            acc += __shfl_xor_sync(0xffffffffu, acc, 2);
            if (lr == 0) sm.qrelS[rloc][jb] = acc;
        }
    }
    __syncthreads();

    float O0[8][4] = {}, O1[8][4] = {};
    float lS[4] = {}, bsS[4][NB_] = {};
    const int rmin = q0 + rw;

    for (int kt = 0; kt < S_ / 32; kt++) {
        const int k0 = kt << 5;
        const int cur = kt & 1;
        CP_WAIT0();
        __syncthreads();
        if (kt + 1 < S_ / 32) { load_kv(cur ^ 1, k0 + 32); CP_COMMIT(); }

        const float (*Kc)[68] = sm.Ks[cur];
        const float (*Vc)[72] = sm.Vs[cur];

        float s0[4][4] = {}, s1[4][4] = {};
        #pragma unroll
        for (int kf = 0; kf < 8; kf++) {
            #pragma unroll
            for (int nf = 0; nf < 4; nf++) {
                float b0 = Kc[(nf << 3) + qd][(kf << 3) + lr];
                float b1 = Kc[(nf << 3) + qd][(kf << 3) + lr + 4];
                mma8f(s0[nf], qf[0][kf], b0, b1);
                mma8f(s1[nf], qf[1][kf], b0, b1);
            }
        }

        bool mixed = (k0 > rmin - 34) && (k0 < rmin + 34);

        #pragma unroll
        for (int h = 0; h < 2; h++) {
            float (*s)[4] = (h == 0) ? s0 : s1;
            int stA = h << 1, stB = stA + 1;
            int rlA = rw + (h << 4) + qd;
            int rgA = q0 + rlA, rgB = rgA + 8;
            float rsA = 0.f, rsB = 0.f;

            if (!mixed) {
                const int bkt = (k0 >= rmin + 34) ? 4 : 0;
                float cA = sm.qrelS[rlA][bkt] * ALPHA_;
                float cB = sm.qrelS[rlA + 8][bkt] * ALPHA_;
                #pragma unroll
                for (int nf = 0; nf < 4; nf++) {
                    float p0 = exp2p(fmaf(s[nf][0], ALPHA_, cA));
                    float p1 = exp2p(fmaf(s[nf][1], ALPHA_, cA));
                    float p2 = exp2p(fmaf(s[nf][2], ALPHA_, cB));
                    float p3 = exp2p(fmaf(s[nf][3], ALPHA_, cB));
                    s[nf][0] = p0; s[nf][1] = p1; s[nf][2] = p2; s[nf][3] = p3;
                    rsA += p0 + p1; rsB += p2 + p3;
                }
                lS[stA] += rsA; lS[stB] += rsB;
                bsS[stA][bkt] += rsA; bsS[stB][bkt] += rsB;
            } else {
                #pragma unroll
                for (int nf = 0; nf < 4; nf++) {
                    #pragma unroll
                    for (int e = 0; e < 4; e++) {
                        int kp = k0 + (nf << 3) + (lr << 1) + (e & 1);
                        int rg = (e < 2) ? rgA : rgB;
                        int rl = (e < 2) ? rlA : rlA + 8;
                        int jb = min(max(kp - rg, -2), 2) + 2;
                        float p = exp2p((s[nf][e] + sm.qrelS[rl][jb]) * ALPHA_);
                        s[nf][e] = p;
                        if (e < 2) { rsA += p; bsS[stA][jb] += p; }
                        else       { rsB += p; bsS[stB][jb] += p; }
                    }
                }
                lS[stA] += rsA; lS[stB] += rsB;
            }
        }

        #pragma unroll
        for (int j = 0; j < 4; j++) {
            float a0[4], a1[4];
            {
                float c0 = f2tff(s0[j][0]), c1 = f2tff(s0[j][1]);
                float c2 = f2tff(s0[j][2]), c3 = f2tff(s0[j][3]);
                float t00 = __shfl_sync(0xffffffffu, c0, src0);
                float t10 = __shfl_sync(0xffffffffu, c1, src0);
                float t20 = __shfl_sync(0xffffffffu, c2, src0);
                float t30 = __shfl_sync(0xffffffffu, c3, src0);
                float t01 = __shfl_sync(0xffffffffu, c0, src1);
                float t11 = __shfl_sync(0xffffffffu, c1, src1);
                float t21 = __shfl_sync(0xffffffffu, c2, src1);
                float t31 = __shfl_sync(0xffffffffu, c3, src1);
                a0[0] = odd ? t10 : t00; a0[1] = odd ? t30 : t20;
                a0[2] = odd ? t11 : t01; a0[3] = odd ? t31 : t21;
            }
            {
                float c0 = f2tff(s1[j][0]), c1 = f2tff(s1[j][1]);
                float c2 = f2tff(s1[j][2]), c3 = f2tff(s1[j][3]);
                float t00 = __shfl_sync(0xffffffffu, c0, src0);
                float t10 = __shfl_sync(0xffffffffu, c1, src0);
                float t20 = __shfl_sync(0xffffffffu, c2, src0);
                float t30 = __shfl_sync(0xffffffffu, c3, src0);
                float t01 = __shfl_sync(0xffffffffu, c0, src1);
                float t11 = __shfl_sync(0xffffffffu, c1, src1);
                float t21 = __shfl_sync(0xffffffffu, c2, src1);
                float t31 = __shfl_sync(0xffffffffu, c3, src1);
                a1[0] = odd ? t10 : t00; a1[1] = odd ? t30 : t20;
                a1[2] = odd ? t11 : t01; a1[3] = odd ? t31 : t21;
            }
            #pragma unroll
            for (int nf = 0; nf < 8; nf++) {
                float b0 = Vc[(j << 3) + lr][(nf << 3) + qd];
                float b1 = Vc[(j << 3) + lr + 4][(nf << 3) + qd];
                mma8f(O0[nf], a0, b0, b1);
                mma8f(O1[nf], a1, b0, b1);
            }
        }
    }

    #pragma unroll
    for (int st = 0; st < 4; st++) {
        #pragma unroll
        for (int o = 1; o <= 2; o <<= 1) {
            lS[st] += __shfl_xor_sync(0xffffffffu, lS[st], o);
            #pragma unroll
            for (int jb = 0; jb < NB_; jb++)
                bsS[st][jb] += __shfl_xor_sync(0xffffffffu, bsS[st][jb], o);
        }
    }

    const int bb = bh / H_, hh = bh % H_;
    #pragma unroll
    for (int h = 0; h < 2; h++) {
        float (*Oh)[4] = (h == 0) ? O0 : O1;
        #pragma unroll
        for (int rp = 0; rp < 2; rp++) {
            int st = (h << 1) + rp;
            float inv = 1.f / lS[st];
            int rg = q0 + rw + (h << 4) + qd + (rp << 3);
            #pragma unroll
            for (int nf = 0; nf < 8; nf++) {
                int d0 = (nf << 3) + (lr << 1);
                float o2a = 0.f, o2b = 0.f;
                #pragma unroll
                for (int jb = 0; jb < NB_; jb++) {
                    o2a += bsS[st][jb] * sm.rvS[jb][d0];
                    o2b += bsS[st][jb] * sm.rvS[jb][d0 + 1];
                }
                float2 w = make_float2(f2tff((Oh[nf][(rp << 1)] + o2a) * inv),
                                       f2tff((Oh[nf][(rp << 1) + 1] + o2b) * inv));
                *(float2*)&g_att[(((size_t)bb * S_ + rg) * H_ + hh) * D_ + d0] = w;
            }
        }
    }
}

// ---------------------------------------------------------------------------
extern "C" void kernel_launch(void* const* d_in, const int* in_sizes, int n_in,
                              void* d_out, int out_size) {
    const float* x    = (const float*)d_in[0];
    const float* Wq   = (const float*)d_in[1];
    const float* bq   = (const float*)d_in[2];
    const float* Wk   = (const float*)d_in[3];
    const float* bk   = (const float*)d_in[4];
    const float* Wv   = (const float*)d_in[5];
    const float* bv   = (const float*)d_in[6];
    const float* Wo   = (const float*)d_in[7];
    const float* bo   = (const float*)d_in[8];
    const float* relk = (const float*)d_in[9];
    const float* relv = (const float*)d_in[10];
    float* out = (float*)d_out;

    float *gq, *gk, *gv, *gatt, *gxr;
    cudaGetSymbolAddress((void**)&gq,   g_q);
    cudaGetSymbolAddress((void**)&gk,   g_k);
    cudaGetSymbolAddress((void**)&gv,   g_v);
    cudaGetSymbolAddress((void**)&gatt, g_att);
    cudaGetSymbolAddress((void**)&gxr,  g_xr);

    cudaFuncSetAttribute(gemm_qkv, cudaFuncAttributeMaxDynamicSharedMemorySize,
                         (int)sizeof(GSmem));
    cudaFuncSetAttribute(gemm_out, cudaFuncAttributeMaxDynamicSharedMemorySize,
                         (int)sizeof(GSmem));
    cudaFuncSetAttribute(attn_tf32, cudaFuncAttributeMaxDynamicSharedMemorySize,
                         (int)sizeof(ASmem));

    round_pass<<<2048, 256>>>(x, Wq, Wk, Wv, Wo);

    gemm_qkv<<<dim3(DM_ / 128, (B_ * S_) / 128, 3), 128, sizeof(GSmem)>>>(
        gxr, bq, bk, bv, gq, gk, gv);
    attn_tf32<<<dim3(S_ / 128, B_ * H_), 128, sizeof(ASmem)>>>(relk, relv);
    gemm_out<<<dim3(DM_ / 128, (B_ * S_) / 128), 128, sizeof(GSmem)>>>(gatt, bo, out);
}